// round 12
// baseline (speedup 1.0000x reference)
#include <cuda_runtime.h>
#include <math.h>

#define NB      16          // batch rows
#define NSAMP   262144      // samples per row
#define NSTAGE  16          // biquads in the chain
#define TPB     256         // threads per block (8 warps)
#define LSUB    32          // samples per thread
#define CHUNK   (TPB*LSUB)  // 8192 samples per block
#define NCHUNK  (NSAMP/CHUNK) // 32 chunks per row
#define PAD     (TPB+1)     // smem transpose pad (conflict-free)
#define NLEV    8           // scan levels (log2 TPB)

// libdevice intrinsics (exactly what XLA lowers jnp f32 transcendentals to)
extern "C" {
    __device__ float __nv_sinf(float);
    __device__ float __nv_cosf(float);
    __device__ float __nv_expf(float);
    __device__ float __nv_powf(float, float);
    __device__ float __nv_sqrtf(float);
}

// ---- scratch (no allocations allowed; __device__ globals) ----
__device__ float4  g_cAf[NSTAGE*NB];        // b0,b1,b2,a1 (f32, JAX-mimicked)
__device__ float   g_cBf[NSTAGE*NB];        // a2 (f32)
__device__ double4 g_Wd[NSTAGE*NB*9];       // T^(32*2^d), d=0..8 (fp64)
__device__ float   g_ginf[NB], g_goutf[NB];
__device__ double  g_agg[NSTAGE*NB*NCHUNK*2];   // block aggregates (fp64)
__device__ int     g_flag[NSTAGE*NB*NCHUNK];

// f32 constants exactly as XLA materializes the python f64 scalars
#define F_2PI      ((float)6.283185307179586)
#define F_FS       (96000.0f)
#define F_LOG_HPF_LO   ((float)2.995732273553991)   // log 20
#define F_LOG_HPF_D    ((float)3.2188758248682006)  // log 25
#define F_LOG_LPF_LO   ((float)8.517193191416238)   // log 5000
#define F_LOG_LPF_D    ((float)1.3862943611198906)  // log 4
#define F_LOG_SHF_LO   ((float)3.912023005428146)   // log 50
#define F_LOG_SHF_D    ((float)5.768320995793772)   // log 320
#define F_LOG_PK_LO    ((float)4.605170185988092)   // log 100
#define F_LOG_PK_D     ((float)5.010635294096256)   // log 150
#define F_LOG_Q_LO     ((float)-0.6931471805599453) // log 0.5
#define F_LOG_Q_D      ((float)3.4657359027997265)  // log 32

__device__ __forceinline__ float denorm_log_f(float n, float llo, float ld) {
    return __nv_expf(__fadd_rn(llo, __fmul_rn(n, ld)));
}

// ---------------------------------------------------------------------------
// Kernel 0: coefficients in f32 bit-mimicking the JAX reference; T-powers in
// fp64 derived FROM the f32-rounded coefficients; flag reset per replay.
// ---------------------------------------------------------------------------
__global__ void coef_kernel(const float* __restrict__ params)
{
    int tid = threadIdx.x;
    if (tid >= NSTAGE*NB) return;
    int stage = tid >> 4;
    int row   = tid & 15;
    const float* p = params + row*50;
    float fn = p[stage*3+0];
    float gn = p[stage*3+1];
    float qn = p[stage*3+2];

    float Q   = denorm_log_f(qn, F_LOG_Q_LO, F_LOG_Q_D);
    float gdb = __fadd_rn(-24.0f, __fmul_rn(gn, 48.0f));

    float b0,b1,b2,a0,a1,a2;

    if (stage == 0) {                 // highpass
        float fc = denorm_log_f(fn, F_LOG_HPF_LO, F_LOG_HPF_D);
        float w0 = __fdiv_rn(__fmul_rn(F_2PI, fc), F_FS);
        float al = __fdiv_rn(__nv_sinf(w0), __fmul_rn(2.0f, Q));
        float c  = __nv_cosf(w0);
        float t  = __fadd_rn(1.0f, c);
        b0 = __fdiv_rn(t, 2.0f);
        b1 = -t;
        b2 = b0;
        a0 = __fadd_rn(1.0f, al);
        a1 = __fmul_rn(-2.0f, c);
        a2 = __fsub_rn(1.0f, al);
    } else if (stage == 15) {         // lowpass
        float fc = denorm_log_f(fn, F_LOG_LPF_LO, F_LOG_LPF_D);
        float w0 = __fdiv_rn(__fmul_rn(F_2PI, fc), F_FS);
        float al = __fdiv_rn(__nv_sinf(w0), __fmul_rn(2.0f, Q));
        float c  = __nv_cosf(w0);
        float t  = __fsub_rn(1.0f, c);
        b0 = __fdiv_rn(t, 2.0f);
        b1 = t;
        b2 = b0;
        a0 = __fadd_rn(1.0f, al);
        a1 = __fmul_rn(-2.0f, c);
        a2 = __fsub_rn(1.0f, al);
    } else if (stage == 1) {          // lowshelf
        float A  = __nv_powf(10.0f, __fdiv_rn(gdb, 40.0f));
        float fc = denorm_log_f(fn, F_LOG_SHF_LO, F_LOG_SHF_D);
        float w0 = __fdiv_rn(__fmul_rn(F_2PI, fc), F_FS);
        float al = __fdiv_rn(__nv_sinf(w0), __fmul_rn(2.0f, Q));
        float c  = __nv_cosf(w0);
        float sA = __nv_sqrtf(A);
        float ap1 = __fadd_rn(A, 1.0f);
        float am1 = __fsub_rn(A, 1.0f);
        float am1c = __fmul_rn(am1, c);
        float ap1c = __fmul_rn(ap1, c);
        float s2a  = __fmul_rn(__fmul_rn(2.0f, sA), al);
        b0 = __fmul_rn(A, __fadd_rn(__fsub_rn(ap1, am1c), s2a));
        b1 = __fmul_rn(__fmul_rn(2.0f, A), __fsub_rn(am1, ap1c));
        b2 = __fmul_rn(A, __fsub_rn(__fsub_rn(ap1, am1c), s2a));
        a0 = __fadd_rn(__fadd_rn(ap1, am1c), s2a);
        a1 = __fmul_rn(-2.0f, __fadd_rn(am1, ap1c));
        a2 = __fsub_rn(__fadd_rn(ap1, am1c), s2a);
    } else if (stage == 14) {         // highshelf
        float A  = __nv_powf(10.0f, __fdiv_rn(gdb, 40.0f));
        float fc = denorm_log_f(fn, F_LOG_SHF_LO, F_LOG_SHF_D);
        float w0 = __fdiv_rn(__fmul_rn(F_2PI, fc), F_FS);
        float al = __fdiv_rn(__nv_sinf(w0), __fmul_rn(2.0f, Q));
        float c  = __nv_cosf(w0);
        float sA = __nv_sqrtf(A);
        float ap1 = __fadd_rn(A, 1.0f);
        float am1 = __fsub_rn(A, 1.0f);
        float am1c = __fmul_rn(am1, c);
        float ap1c = __fmul_rn(ap1, c);
        float s2a  = __fmul_rn(__fmul_rn(2.0f, sA), al);
        b0 = __fmul_rn(A, __fadd_rn(__fadd_rn(ap1, am1c), s2a));
        b1 = __fmul_rn(__fmul_rn(-2.0f, A), __fadd_rn(am1, ap1c));
        b2 = __fmul_rn(A, __fsub_rn(__fadd_rn(ap1, am1c), s2a));
        a0 = __fadd_rn(__fsub_rn(ap1, am1c), s2a);
        a1 = __fmul_rn(2.0f, __fsub_rn(am1, ap1c));
        a2 = __fsub_rn(__fsub_rn(ap1, am1c), s2a);
    } else {                          // peak
        float A  = __nv_powf(10.0f, __fdiv_rn(gdb, 40.0f));
        float fc = denorm_log_f(fn, F_LOG_PK_LO, F_LOG_PK_D);
        float w0 = __fdiv_rn(__fmul_rn(F_2PI, fc), F_FS);
        float al = __fdiv_rn(__nv_sinf(w0), __fmul_rn(2.0f, Q));
        float c  = __nv_cosf(w0);
        float aA  = __fmul_rn(al, A);
        float adA = __fdiv_rn(al, A);
        b0 = __fadd_rn(1.0f, aA);
        b1 = __fmul_rn(-2.0f, c);
        b2 = __fsub_rn(1.0f, aA);
        a0 = __fadd_rn(1.0f, adA);
        a1 = __fmul_rn(-2.0f, c);
        a2 = __fsub_rn(1.0f, adA);
    }

    float nb0 = __fdiv_rn(b0, a0);
    float nb1 = __fdiv_rn(b1, a0);
    float nb2 = __fdiv_rn(b2, a0);
    float na1 = __fdiv_rn(a1, a0);
    float na2 = __fdiv_rn(a2, a0);

    g_cAf[tid] = make_float4(nb0, nb1, nb2, na1);
    g_cBf[tid] = na2;

    // T = [[-a1,1],[-a2,0]] from the f32 coefficients; powers in fp64.
    // Store T^(32*2^d), d=0..8  (T^32 after 5 squarings; 9 entries up to T^8192)
    double ia1=(double)na1, ia2=(double)na2;
    double m00=-ia1, m01=1.0, m10=-ia2, m11=0.0;
    for (int k=0;k<5;k++){
        double n00 = m00*m00 + m01*m10, n01 = m00*m01 + m01*m11;
        double n10 = m10*m00 + m11*m10, n11 = m10*m01 + m11*m11;
        m00=n00;m01=n01;m10=n10;m11=n11;
    }
    for (int d=0;d<9;d++){
        double4 w; w.x=m00; w.y=m01; w.z=m10; w.w=m11;
        g_Wd[tid*9+d] = w;
        double n00 = m00*m00 + m01*m10, n01 = m00*m01 + m01*m11;
        double n10 = m10*m00 + m11*m10, n11 = m10*m01 + m11*m11;
        m00=n00;m01=n01;m10=n10;m11=n11;
    }
    for (int c=0;c<NCHUNK;c++) g_flag[tid*NCHUNK + c] = 0;
    if (stage == 0) {
        float indb  = __fadd_rn(-60.0f, __fmul_rn(p[48], 60.0f));
        float outdb = __fadd_rn(-60.0f, __fmul_rn(p[49], 60.0f));
        g_ginf[row]  = __nv_powf(10.0f, __fdiv_rn(indb, 20.0f));
        g_goutf[row] = __nv_powf(10.0f, __fdiv_rn(outdb, 20.0f));
    }
}

// ---------------------------------------------------------------------------
// Fused kernel, TPB=256 / LSUB=32: 8 warps per block (2x latency-hiding pool
// vs TPB=128), half the per-thread serial recursion depth, ping-pong scan
// buffers (1 barrier per level). Tile resident in smem across all 16 stages;
// only cross-block traffic is the 16-byte per-(stage,chunk) aggregate.
// ---------------------------------------------------------------------------
__global__ void __launch_bounds__(TPB)
fused_kernel(const float* __restrict__ audio, float* __restrict__ out)
{
    __shared__ float   sx[LSUB*PAD];          // resident sample tile (~33 KB)
    __shared__ double  sv1[2*TPB], sv2[2*TPB];// ping-pong scan states (8 KB)
    __shared__ double4 sW[9];
    __shared__ double  sEntry[2];

    int bx    = blockIdx.x;
    int row   = bx & (NB-1);
    int chunk = bx >> 4;
    int t     = threadIdx.x;

    size_t base = (size_t)row*NSAMP + (size_t)chunk*CHUNK;
    float ginf  = g_ginf[row];
    float goutf = g_goutf[row];

    // one-time coalesced load + transpose, with f32 input gain (as reference)
    for (int k = t; k < CHUNK; k += TPB) {
        float x = __fmul_rn(audio[base + k], ginf);
        sx[(k & (LSUB-1))*PAD + (k >> 5)] = x;
    }

    for (int stage = 0; stage < NSTAGE; stage++) {
        int rs = stage*NB + row;

        __syncthreads();                      // sx ready / sW reusable
        if (t < 9) sW[t] = g_Wd[rs*9 + t];
        float4 c4 = g_cAf[rs];
        float b0=c4.x, b1=c4.y, b2=c4.z, a1=c4.w;
        float a2c = g_cBf[rs];
        __syncthreads();

        // ---- pass 1: fp32 recursion from zero state (own smem column) -----
        float s1 = 0.f, s2 = 0.f;
        #pragma unroll
        for (int i = 0; i < LSUB; i++) {
            float x = sx[i*PAD + t];
            float y = fmaf(b0, x, s1);
            s1 = fmaf(-a1, y, fmaf(b1, x, s2));
            s2 = fmaf(b2, x, -a2c*y);
        }
        double v1 = (double)s1, v2 = (double)s2;
        int pp = 0;
        sv1[t] = v1; sv2[t] = v2;
        __syncthreads();

        // ---- intra-block affine scan, fp64, ping-pong (1 bar/level) -------
        #pragma unroll
        for (int d = 0; d < NLEV; d++) {
            int o = 1 << d;
            if (t >= o) {
                double p1 = sv1[pp*TPB + t-o];
                double p2 = sv2[pp*TPB + t-o];
                double4 W = sW[d];
                v1 = fma(W.x, p1, fma(W.y, p2, v1));
                v2 = fma(W.z, p1, fma(W.w, p2, v2));
            }
            sv1[(pp^1)*TPB + t] = v1;
            sv2[(pp^1)*TPB + t] = v2;
            __syncthreads();
            pp ^= 1;
        }

        // ---- publish block aggregate for this stage -----------------------
        int aidx = rs*NCHUNK + chunk;
        if (t == TPB-1) {
            g_agg[2*aidx+0] = v1;
            g_agg[2*aidx+1] = v2;
            __threadfence();
            atomicExch(&g_flag[aidx], 1);
        }

        // ---- decoupled lookback (warp 0): fp64 Horner over predecessors ---
        if (t < 32) {
            double e1 = 0.0, e2 = 0.0;
            if (chunk > 0) {
                double a1v = 0.0, a2v = 0.0;
                if (t < chunk) {
                    int idx = rs*NCHUNK + t;
                    volatile int* fl = g_flag;
                    while (fl[idx] == 0) __nanosleep(40);
                    __threadfence();
                    volatile double* ag = g_agg;
                    a1v = ag[2*idx+0];
                    a2v = ag[2*idx+1];
                }
                __syncwarp();
                double4 Tb = sW[8];                 // T^CHUNK (fp64)
                double acc1 = 0.0, acc2 = 0.0;      // S = sum Tb^{c-1-k} v_k
                for (int k = 0; k < chunk; k++) {
                    double u1 = __shfl_sync(0xffffffffu, a1v, k);
                    double u2 = __shfl_sync(0xffffffffu, a2v, k);
                    double n1 = fma(Tb.x, acc1, fma(Tb.y, acc2, u1));
                    double n2 = fma(Tb.z, acc1, fma(Tb.w, acc2, u2));
                    acc1 = n1; acc2 = n2;
                }
                e1 = acc1; e2 = acc2;
            }
            if (t == 0) { sEntry[0] = e1; sEntry[1] = e2; }
        }
        __syncthreads();

        // ---- thread entry state: T^(32*t) * e_block + local excl. prefix --
        double e1 = sEntry[0], e2 = sEntry[1];
        #pragma unroll
        for (int d = 0; d < NLEV; d++) {
            if (t & (1 << d)) {
                double4 W = sW[d];
                double n1 = fma(W.x, e1, W.y*e2);
                double n2 = fma(W.z, e1, W.w*e2);
                e1 = n1; e2 = n2;
            }
        }
        s1 = (float)(e1 + ((t > 0) ? sv1[pp*TPB + t-1] : 0.0));
        s2 = (float)(e2 + ((t > 0) ? sv2[pp*TPB + t-1] : 0.0));

        // ---- replay fp32 recursion, write y back into own smem column -----
        #pragma unroll
        for (int i = 0; i < LSUB; i++) {
            float x = sx[i*PAD + t];
            float y = fmaf(b0, x, s1);
            s1 = fmaf(-a1, y, fmaf(b1, x, s2));
            s2 = fmaf(b2, x, -a2c*y);
            if (stage == NSTAGE-1) y = __fmul_rn(y, goutf);
            sx[i*PAD + t] = y;
        }
        // loop-top __syncthreads() orders replay writes vs next stage
    }

    __syncthreads();
    // one-time coalesced store
    for (int k = t; k < CHUNK; k += TPB)
        out[base + k] = sx[(k & (LSUB-1))*PAD + (k >> 5)];
}

// ---------------------------------------------------------------------------
extern "C" void kernel_launch(void* const* d_in, const int* in_sizes, int n_in,
                              void* d_out, int out_size)
{
    const float* audio  = (const float*)d_in[0];   // [16, 262144] f32
    const float* params = (const float*)d_in[1];   // [16, 50]     f32
    float* out = (float*)d_out;

    coef_kernel<<<1, NSTAGE*NB>>>(params);
    fused_kernel<<<NB*NCHUNK, TPB>>>(audio, out);
}

// round 14
// speedup vs baseline: 1.8210x; 1.8210x over previous
#include <cuda_runtime.h>
#include <math.h>

#define NB      16          // batch rows
#define NSAMP   262144      // samples per row
#define NSTAGE  16          // biquads in the chain
#define TPB     128         // threads per block (4 warps) — proven config
#define LSUB    64          // samples per thread
#define CHUNK   (TPB*LSUB)  // 8192 samples per block
#define NCHUNK  (NSAMP/CHUNK) // 32 chunks per row
#define PAD     129         // smem transpose pad (conflict-free)

// libdevice intrinsics (exactly what XLA lowers jnp f32 transcendentals to)
extern "C" {
    __device__ float __nv_sinf(float);
    __device__ float __nv_cosf(float);
    __device__ float __nv_expf(float);
    __device__ float __nv_powf(float, float);
    __device__ float __nv_sqrtf(float);
}

// ---- scratch (no allocations allowed; __device__ globals) ----
__device__ float4  g_cAf[NSTAGE*NB];        // b0,b1,b2,a1 (f32, JAX-mimicked)
__device__ float   g_cBf[NSTAGE*NB];        // a2 (f32)
__device__ double4 g_Wd[NSTAGE*NB*8];       // T^(64*2^d), d=0..7 (fp64)
__device__ double4 g_Tpow[NSTAGE*NB*32];    // Tb^j, j=0..31, Tb=T^8192 (fp64)
__device__ float   g_ginf[NB], g_goutf[NB];
__device__ double  g_agg[NSTAGE*NB*NCHUNK*2];   // block aggregates (fp64)
__device__ int     g_flag[NSTAGE*NB*NCHUNK];

// f32 constants exactly as XLA materializes the python f64 scalars
#define F_2PI      ((float)6.283185307179586)
#define F_FS       (96000.0f)
#define F_LOG_HPF_LO   ((float)2.995732273553991)   // log 20
#define F_LOG_HPF_D    ((float)3.2188758248682006)  // log 25
#define F_LOG_LPF_LO   ((float)8.517193191416238)   // log 5000
#define F_LOG_LPF_D    ((float)1.3862943611198906)  // log 4
#define F_LOG_SHF_LO   ((float)3.912023005428146)   // log 50
#define F_LOG_SHF_D    ((float)5.768320995793772)   // log 320
#define F_LOG_PK_LO    ((float)4.605170185988092)   // log 100
#define F_LOG_PK_D     ((float)5.010635294096256)   // log 150
#define F_LOG_Q_LO     ((float)-0.6931471805599453) // log 0.5
#define F_LOG_Q_D      ((float)3.4657359027997265)  // log 32

__device__ __forceinline__ float denorm_log_f(float n, float llo, float ld) {
    return __nv_expf(__fadd_rn(llo, __fmul_rn(n, ld)));
}

// ---------------------------------------------------------------------------
// Kernel 0: f32 JAX-mimicked coefficients; fp64 T-powers T^(64*2^d) and the
// lookback power table Tb^j; flag reset per graph replay.
// ---------------------------------------------------------------------------
__global__ void coef_kernel(const float* __restrict__ params)
{
    int tid = threadIdx.x;
    if (tid >= NSTAGE*NB) return;
    int stage = tid >> 4;
    int row   = tid & 15;
    const float* p = params + row*50;
    float fn = p[stage*3+0];
    float gn = p[stage*3+1];
    float qn = p[stage*3+2];

    float Q   = denorm_log_f(qn, F_LOG_Q_LO, F_LOG_Q_D);
    float gdb = __fadd_rn(-24.0f, __fmul_rn(gn, 48.0f));

    float b0,b1,b2,a0,a1,a2;

    if (stage == 0) {                 // highpass
        float fc = denorm_log_f(fn, F_LOG_HPF_LO, F_LOG_HPF_D);
        float w0 = __fdiv_rn(__fmul_rn(F_2PI, fc), F_FS);
        float al = __fdiv_rn(__nv_sinf(w0), __fmul_rn(2.0f, Q));
        float c  = __nv_cosf(w0);
        float t  = __fadd_rn(1.0f, c);
        b0 = __fdiv_rn(t, 2.0f);
        b1 = -t;
        b2 = b0;
        a0 = __fadd_rn(1.0f, al);
        a1 = __fmul_rn(-2.0f, c);
        a2 = __fsub_rn(1.0f, al);
    } else if (stage == 15) {         // lowpass
        float fc = denorm_log_f(fn, F_LOG_LPF_LO, F_LOG_LPF_D);
        float w0 = __fdiv_rn(__fmul_rn(F_2PI, fc), F_FS);
        float al = __fdiv_rn(__nv_sinf(w0), __fmul_rn(2.0f, Q));
        float c  = __nv_cosf(w0);
        float t  = __fsub_rn(1.0f, c);
        b0 = __fdiv_rn(t, 2.0f);
        b1 = t;
        b2 = b0;
        a0 = __fadd_rn(1.0f, al);
        a1 = __fmul_rn(-2.0f, c);
        a2 = __fsub_rn(1.0f, al);
    } else if (stage == 1) {          // lowshelf
        float A  = __nv_powf(10.0f, __fdiv_rn(gdb, 40.0f));
        float fc = denorm_log_f(fn, F_LOG_SHF_LO, F_LOG_SHF_D);
        float w0 = __fdiv_rn(__fmul_rn(F_2PI, fc), F_FS);
        float al = __fdiv_rn(__nv_sinf(w0), __fmul_rn(2.0f, Q));
        float c  = __nv_cosf(w0);
        float sA = __nv_sqrtf(A);
        float ap1 = __fadd_rn(A, 1.0f);
        float am1 = __fsub_rn(A, 1.0f);
        float am1c = __fmul_rn(am1, c);
        float ap1c = __fmul_rn(ap1, c);
        float s2a  = __fmul_rn(__fmul_rn(2.0f, sA), al);
        b0 = __fmul_rn(A, __fadd_rn(__fsub_rn(ap1, am1c), s2a));
        b1 = __fmul_rn(__fmul_rn(2.0f, A), __fsub_rn(am1, ap1c));
        b2 = __fmul_rn(A, __fsub_rn(__fsub_rn(ap1, am1c), s2a));
        a0 = __fadd_rn(__fadd_rn(ap1, am1c), s2a);
        a1 = __fmul_rn(-2.0f, __fadd_rn(am1, ap1c));
        a2 = __fsub_rn(__fadd_rn(ap1, am1c), s2a);
    } else if (stage == 14) {         // highshelf
        float A  = __nv_powf(10.0f, __fdiv_rn(gdb, 40.0f));
        float fc = denorm_log_f(fn, F_LOG_SHF_LO, F_LOG_SHF_D);
        float w0 = __fdiv_rn(__fmul_rn(F_2PI, fc), F_FS);
        float al = __fdiv_rn(__nv_sinf(w0), __fmul_rn(2.0f, Q));
        float c  = __nv_cosf(w0);
        float sA = __nv_sqrtf(A);
        float ap1 = __fadd_rn(A, 1.0f);
        float am1 = __fsub_rn(A, 1.0f);
        float am1c = __fmul_rn(am1, c);
        float ap1c = __fmul_rn(ap1, c);
        float s2a  = __fmul_rn(__fmul_rn(2.0f, sA), al);
        b0 = __fmul_rn(A, __fadd_rn(__fadd_rn(ap1, am1c), s2a));
        b1 = __fmul_rn(__fmul_rn(-2.0f, A), __fadd_rn(am1, ap1c));
        b2 = __fmul_rn(A, __fsub_rn(__fadd_rn(ap1, am1c), s2a));
        a0 = __fadd_rn(__fsub_rn(ap1, am1c), s2a);
        a1 = __fmul_rn(2.0f, __fsub_rn(am1, ap1c));
        a2 = __fsub_rn(__fsub_rn(ap1, am1c), s2a);
    } else {                          // peak
        float A  = __nv_powf(10.0f, __fdiv_rn(gdb, 40.0f));
        float fc = denorm_log_f(fn, F_LOG_PK_LO, F_LOG_PK_D);
        float w0 = __fdiv_rn(__fmul_rn(F_2PI, fc), F_FS);
        float al = __fdiv_rn(__nv_sinf(w0), __fmul_rn(2.0f, Q));
        float c  = __nv_cosf(w0);
        float aA  = __fmul_rn(al, A);
        float adA = __fdiv_rn(al, A);
        b0 = __fadd_rn(1.0f, aA);
        b1 = __fmul_rn(-2.0f, c);
        b2 = __fsub_rn(1.0f, aA);
        a0 = __fadd_rn(1.0f, adA);
        a1 = __fmul_rn(-2.0f, c);
        a2 = __fsub_rn(1.0f, adA);
    }

    float nb0 = __fdiv_rn(b0, a0);
    float nb1 = __fdiv_rn(b1, a0);
    float nb2 = __fdiv_rn(b2, a0);
    float na1 = __fdiv_rn(a1, a0);
    float na2 = __fdiv_rn(a2, a0);

    g_cAf[tid] = make_float4(nb0, nb1, nb2, na1);
    g_cBf[tid] = na2;

    // T = [[-a1,1],[-a2,0]]; powers T^(64*2^d), d=0..7, fp64.
    double ia1=(double)na1, ia2=(double)na2;
    double m00=-ia1, m01=1.0, m10=-ia2, m11=0.0;
    for (int k=0;k<6;k++){
        double n00 = m00*m00 + m01*m10, n01 = m00*m01 + m01*m11;
        double n10 = m10*m00 + m11*m10, n11 = m10*m01 + m11*m11;
        m00=n00;m01=n01;m10=n10;m11=n11;
    }
    double t00=0,t01=0,t10=0,t11=0;   // Tb = T^8192 (captured at d=7)
    for (int d=0;d<8;d++){
        double4 w; w.x=m00; w.y=m01; w.z=m10; w.w=m11;
        g_Wd[tid*8+d] = w;
        if (d == 7) { t00=m00; t01=m01; t10=m10; t11=m11; }
        double n00 = m00*m00 + m01*m10, n01 = m00*m01 + m01*m11;
        double n10 = m10*m00 + m11*m10, n11 = m10*m01 + m11*m11;
        m00=n00;m01=n01;m10=n10;m11=n11;
    }
    // Tb^j, j=0..31 (P_{j+1} = Tb * P_j)
    double p00=1.0, p01=0.0, p10=0.0, p11=1.0;
    for (int j=0;j<32;j++){
        double4 w; w.x=p00; w.y=p01; w.z=p10; w.w=p11;
        g_Tpow[tid*32+j] = w;
        double n00 = t00*p00 + t01*p10, n01 = t00*p01 + t01*p11;
        double n10 = t10*p00 + t11*p10, n11 = t10*p01 + t11*p11;
        p00=n00;p01=n01;p10=n10;p11=n11;
    }
    for (int c=0;c<NCHUNK;c++) g_flag[tid*NCHUNK + c] = 0;
    if (stage == 0) {
        float indb  = __fadd_rn(-60.0f, __fmul_rn(p[48], 60.0f));
        float outdb = __fadd_rn(-60.0f, __fmul_rn(p[49], 60.0f));
        g_ginf[row]  = __nv_powf(10.0f, __fdiv_rn(indb, 20.0f));
        g_goutf[row] = __nv_powf(10.0f, __fdiv_rn(outdb, 20.0f));
    }
}

// ---------------------------------------------------------------------------
// Fused kernel (TPB=128): tile resident across all 16 stages. Per stage:
//  - fp32 pass-1 (bit-identical to R11)
//  - intra-warp fp64 affine scan via shuffles (NO barriers)
//  - warp totals -> warp 1 combines + publishes aggregate EARLY
//  - warp 0 does PARALLEL lookback (lane t: Tb^(c-1-t)*V_t, tree-sum)
//  - per-thread entry rotation, fp32 replay (bit-identical)
// 3 barriers per stage (vs ~17 in R11).
// ---------------------------------------------------------------------------
__global__ void __launch_bounds__(TPB)
fused_kernel(const float* __restrict__ audio, float* __restrict__ out)
{
    __shared__ float   sx[LSUB*PAD];        // resident sample tile (~33 KB)
    __shared__ double4 sW[2][8];            // double-buffered stage matrices
    __shared__ double  sWT1[4], sWT2[4];    // warp totals
    __shared__ double  sS1[4], sS2[4];      // per-warp block prefixes
    __shared__ double  sEntry[2];           // block entry state from lookback

    int bx    = blockIdx.x;
    int row   = bx & (NB-1);
    int chunk = bx >> 4;
    int t     = threadIdx.x;
    int wid   = t >> 5;
    int lane  = t & 31;

    size_t base = (size_t)row*NSAMP + (size_t)chunk*CHUNK;
    float ginf  = g_ginf[row];
    float goutf = g_goutf[row];

    // one-time coalesced load + transpose, with f32 input gain (as reference)
    for (int k = t; k < CHUNK; k += TPB) {
        float x = __fmul_rn(audio[base + k], ginf);
        sx[(k & (LSUB-1))*PAD + (k >> 6)] = x;
    }
    // prefetch stage 0 matrices
    if (t < 8) sW[0][t] = g_Wd[(0*NB + row)*8 + t];
    __syncthreads();                               // bar A (pre-loop)

    for (int stage = 0; stage < NSTAGE; stage++) {
        int rs = stage*NB + row;
        int buf = stage & 1;

        float4 c4 = g_cAf[rs];
        float b0=c4.x, b1=c4.y, b2=c4.z, a1=c4.w;
        float a2c = g_cBf[rs];

        // prefetch next stage's matrices into the other buffer
        if (stage+1 < NSTAGE && t < 8)
            sW[buf^1][t] = g_Wd[((stage+1)*NB + row)*8 + t];

        // ---- pass 1: fp32 recursion from zero state (bit-identical) -------
        float s1 = 0.f, s2 = 0.f;
        #pragma unroll 8
        for (int i = 0; i < LSUB; i++) {
            float x = sx[i*PAD + t];
            float y = fmaf(b0, x, s1);
            s1 = fmaf(-a1, y, fmaf(b1, x, s2));
            s2 = fmaf(b2, x, -a2c*y);
        }
        double v1 = (double)s1, v2 = (double)s2;

        // ---- intra-warp affine scan, fp64, via shuffles (no barriers) -----
        #pragma unroll
        for (int d = 0; d < 5; d++) {
            int o = 1 << d;
            double p1 = __shfl_up_sync(0xffffffffu, v1, o);
            double p2 = __shfl_up_sync(0xffffffffu, v2, o);
            if (lane >= o) {
                double4 W = sW[buf][d];
                v1 = fma(W.x, p1, fma(W.y, p2, v1));
                v2 = fma(W.z, p1, fma(W.w, p2, v2));
            }
        }
        // within-warp exclusive prefix (u_{l-1}) for later
        double pl1 = __shfl_up_sync(0xffffffffu, v1, 1);
        double pl2 = __shfl_up_sync(0xffffffffu, v2, 1);
        if (lane == 0) { pl1 = 0.0; pl2 = 0.0; }

        if (lane == 31) { sWT1[wid] = v1; sWT2[wid] = v2; }
        __syncthreads();                           // bar 1: warp totals ready

        // ---- warp 1: combine warp totals, publish aggregate EARLY ---------
        if (wid == 1) {
            if (lane == 0) {
                double4 W5 = sW[buf][5];           // T^2048
                double a1s = 0.0, a2s = 0.0;       // S_w running
                #pragma unroll
                for (int w = 0; w < 4; w++) {
                    sS1[w] = a1s; sS2[w] = a2s;
                    double n1 = fma(W5.x, a1s, fma(W5.y, a2s, sWT1[w]));
                    double n2 = fma(W5.z, a1s, fma(W5.w, a2s, sWT2[w]));
                    a1s = n1; a2s = n2;
                }
                int aidx = rs*NCHUNK + chunk;
                g_agg[2*aidx+0] = a1s;             // block aggregate = S_4
                g_agg[2*aidx+1] = a2s;
                __threadfence();
                atomicExch(&g_flag[aidx], 1);
            }
            __syncwarp();
        }

        // ---- warp 0: PARALLEL lookback (lane t: Tb^(c-1-t) * V_t) ---------
        if (wid == 0) {
            double e1 = 0.0, e2 = 0.0;
            if (chunk > 0) {
                if (lane < chunk) {
                    int idx = rs*NCHUNK + lane;
                    volatile int* fl = g_flag;
                    while (fl[idx] == 0) __nanosleep(40);
                    __threadfence();
                    volatile double* ag = g_agg;
                    double u1 = ag[2*idx+0];
                    double u2 = ag[2*idx+1];
                    double4 M = g_Tpow[rs*32 + (chunk-1-lane)];
                    e1 = fma(M.x, u1, M.y*u2);
                    e2 = fma(M.z, u1, M.w*u2);
                }
                // tree sum over lanes (affine parts add linearly)
                #pragma unroll
                for (int off = 16; off > 0; off >>= 1) {
                    e1 += __shfl_down_sync(0xffffffffu, e1, off);
                    e2 += __shfl_down_sync(0xffffffffu, e2, off);
                }
            }
            if (lane == 0) { sEntry[0] = e1; sEntry[1] = e2; }
        }
        __syncthreads();                           // bar 2: sEntry + sS ready

        // ---- per-thread entry: u_{l-1} + T^(64l)*(S_w + T^(2048w)*e) ------
        double e1 = sEntry[0], e2 = sEntry[1];
        if (wid & 1) {
            double4 W = sW[buf][5];
            double n1 = fma(W.x, e1, W.y*e2);
            double n2 = fma(W.z, e1, W.w*e2);
            e1 = n1; e2 = n2;
        }
        if (wid & 2) {
            double4 W = sW[buf][6];
            double n1 = fma(W.x, e1, W.y*e2);
            double n2 = fma(W.z, e1, W.w*e2);
            e1 = n1; e2 = n2;
        }
        e1 += sS1[wid];
        e2 += sS2[wid];
        #pragma unroll
        for (int d = 0; d < 5; d++) {
            if (lane & (1 << d)) {
                double4 W = sW[buf][d];
                double n1 = fma(W.x, e1, W.y*e2);
                double n2 = fma(W.z, e1, W.w*e2);
                e1 = n1; e2 = n2;
            }
        }
        s1 = (float)(e1 + pl1);
        s2 = (float)(e2 + pl2);

        // ---- replay fp32 recursion, write y back (bit-identical) ----------
        #pragma unroll 8
        for (int i = 0; i < LSUB; i++) {
            float x = sx[i*PAD + t];
            float y = fmaf(b0, x, s1);
            s1 = fmaf(-a1, y, fmaf(b1, x, s2));
            s2 = fmaf(b2, x, -a2c*y);
            if (stage == NSTAGE-1) y = __fmul_rn(y, goutf);
            sx[i*PAD + t] = y;
        }
        __syncthreads();                           // bar 3: sx/smem for next stage
    }

    // one-time coalesced store
    for (int k = t; k < CHUNK; k += TPB)
        out[base + k] = sx[(k & (LSUB-1))*PAD + (k >> 6)];
}

// ---------------------------------------------------------------------------
extern "C" void kernel_launch(void* const* d_in, const int* in_sizes, int n_in,
                              void* d_out, int out_size)
{
    const float* audio  = (const float*)d_in[0];   // [16, 262144] f32
    const float* params = (const float*)d_in[1];   // [16, 50]     f32
    float* out = (float*)d_out;

    coef_kernel<<<1, NSTAGE*NB>>>(params);
    fused_kernel<<<NB*NCHUNK, TPB>>>(audio, out);
}

// round 16
// speedup vs baseline: 1.8212x; 1.0001x over previous
#include <cuda_runtime.h>
#include <math.h>

#define NB      16          // batch rows
#define NSAMP   262144      // samples per row
#define NSTAGE  16          // biquads in the chain
#define TPB     128         // threads per block (4 warps)
#define LSUB    64          // samples per thread
#define CHUNK   (TPB*LSUB)  // 8192 samples per block
#define NCHUNK  (NSAMP/CHUNK) // 32 chunks per row
#define PAD     129         // smem transpose pad (conflict-free)

// libdevice intrinsics (exactly what XLA lowers jnp f32 transcendentals to)
extern "C" {
    __device__ float __nv_sinf(float);
    __device__ float __nv_cosf(float);
    __device__ float __nv_expf(float);
    __device__ float __nv_powf(float, float);
    __device__ float __nv_sqrtf(float);
}

// ---- scratch (no allocations allowed; __device__ globals) ----
__device__ float4  g_cAf[NSTAGE*NB];        // b0, k1, k2, a1 (f32)
__device__ float   g_cBf[NSTAGE*NB];        // a2 (f32)
__device__ double4 g_Wd[NSTAGE*NB*8];       // T^(64*2^d), d=0..7 (fp64)
__device__ double4 g_Tpow[NSTAGE*NB*32];    // Tb^j, j=0..31, Tb=T^8192 (fp64)
__device__ float   g_ginf[NB], g_goutf[NB];
__device__ double  g_agg[NSTAGE*NB*NCHUNK*2];   // block aggregates (fp64)
__device__ int     g_flag[NSTAGE*NB*NCHUNK];

// f32 constants exactly as XLA materializes the python f64 scalars
#define F_2PI      ((float)6.283185307179586)
#define F_FS       (96000.0f)
#define F_LOG_HPF_LO   ((float)2.995732273553991)   // log 20
#define F_LOG_HPF_D    ((float)3.2188758248682006)  // log 25
#define F_LOG_LPF_LO   ((float)8.517193191416238)   // log 5000
#define F_LOG_LPF_D    ((float)1.3862943611198906)  // log 4
#define F_LOG_SHF_LO   ((float)3.912023005428146)   // log 50
#define F_LOG_SHF_D    ((float)5.768320995793772)   // log 320
#define F_LOG_PK_LO    ((float)4.605170185988092)   // log 100
#define F_LOG_PK_D     ((float)5.010635294096256)   // log 150
#define F_LOG_Q_LO     ((float)-0.6931471805599453) // log 0.5
#define F_LOG_Q_D      ((float)3.4657359027997265)  // log 32

__device__ __forceinline__ float denorm_log_f(float n, float llo, float ld) {
    return __nv_expf(__fadd_rn(llo, __fmul_rn(n, ld)));
}

// ---------------------------------------------------------------------------
// Kernel 0: f32 JAX-mimicked coefficients; state-form feed constants k1,k2;
// fp64 T-powers and lookback table; flag reset per graph replay.
// ---------------------------------------------------------------------------
__global__ void coef_kernel(const float* __restrict__ params)
{
    int tid = threadIdx.x;
    if (tid >= NSTAGE*NB) return;
    int stage = tid >> 4;
    int row   = tid & 15;
    const float* p = params + row*50;
    float fn = p[stage*3+0];
    float gn = p[stage*3+1];
    float qn = p[stage*3+2];

    float Q   = denorm_log_f(qn, F_LOG_Q_LO, F_LOG_Q_D);
    float gdb = __fadd_rn(-24.0f, __fmul_rn(gn, 48.0f));

    float b0,b1,b2,a0,a1,a2;

    if (stage == 0) {                 // highpass
        float fc = denorm_log_f(fn, F_LOG_HPF_LO, F_LOG_HPF_D);
        float w0 = __fdiv_rn(__fmul_rn(F_2PI, fc), F_FS);
        float al = __fdiv_rn(__nv_sinf(w0), __fmul_rn(2.0f, Q));
        float c  = __nv_cosf(w0);
        float t  = __fadd_rn(1.0f, c);
        b0 = __fdiv_rn(t, 2.0f);
        b1 = -t;
        b2 = b0;
        a0 = __fadd_rn(1.0f, al);
        a1 = __fmul_rn(-2.0f, c);
        a2 = __fsub_rn(1.0f, al);
    } else if (stage == 15) {         // lowpass
        float fc = denorm_log_f(fn, F_LOG_LPF_LO, F_LOG_LPF_D);
        float w0 = __fdiv_rn(__fmul_rn(F_2PI, fc), F_FS);
        float al = __fdiv_rn(__nv_sinf(w0), __fmul_rn(2.0f, Q));
        float c  = __nv_cosf(w0);
        float t  = __fsub_rn(1.0f, c);
        b0 = __fdiv_rn(t, 2.0f);
        b1 = t;
        b2 = b0;
        a0 = __fadd_rn(1.0f, al);
        a1 = __fmul_rn(-2.0f, c);
        a2 = __fsub_rn(1.0f, al);
    } else if (stage == 1) {          // lowshelf
        float A  = __nv_powf(10.0f, __fdiv_rn(gdb, 40.0f));
        float fc = denorm_log_f(fn, F_LOG_SHF_LO, F_LOG_SHF_D);
        float w0 = __fdiv_rn(__fmul_rn(F_2PI, fc), F_FS);
        float al = __fdiv_rn(__nv_sinf(w0), __fmul_rn(2.0f, Q));
        float c  = __nv_cosf(w0);
        float sA = __nv_sqrtf(A);
        float ap1 = __fadd_rn(A, 1.0f);
        float am1 = __fsub_rn(A, 1.0f);
        float am1c = __fmul_rn(am1, c);
        float ap1c = __fmul_rn(ap1, c);
        float s2a  = __fmul_rn(__fmul_rn(2.0f, sA), al);
        b0 = __fmul_rn(A, __fadd_rn(__fsub_rn(ap1, am1c), s2a));
        b1 = __fmul_rn(__fmul_rn(2.0f, A), __fsub_rn(am1, ap1c));
        b2 = __fmul_rn(A, __fsub_rn(__fsub_rn(ap1, am1c), s2a));
        a0 = __fadd_rn(__fadd_rn(ap1, am1c), s2a);
        a1 = __fmul_rn(-2.0f, __fadd_rn(am1, ap1c));
        a2 = __fsub_rn(__fadd_rn(ap1, am1c), s2a);
    } else if (stage == 14) {         // highshelf
        float A  = __nv_powf(10.0f, __fdiv_rn(gdb, 40.0f));
        float fc = denorm_log_f(fn, F_LOG_SHF_LO, F_LOG_SHF_D);
        float w0 = __fdiv_rn(__fmul_rn(F_2PI, fc), F_FS);
        float al = __fdiv_rn(__nv_sinf(w0), __fmul_rn(2.0f, Q));
        float c  = __nv_cosf(w0);
        float sA = __nv_sqrtf(A);
        float ap1 = __fadd_rn(A, 1.0f);
        float am1 = __fsub_rn(A, 1.0f);
        float am1c = __fmul_rn(am1, c);
        float ap1c = __fmul_rn(ap1, c);
        float s2a  = __fmul_rn(__fmul_rn(2.0f, sA), al);
        b0 = __fmul_rn(A, __fadd_rn(__fadd_rn(ap1, am1c), s2a));
        b1 = __fmul_rn(__fmul_rn(-2.0f, A), __fadd_rn(am1, ap1c));
        b2 = __fmul_rn(A, __fsub_rn(__fadd_rn(ap1, am1c), s2a));
        a0 = __fadd_rn(__fsub_rn(ap1, am1c), s2a);
        a1 = __fmul_rn(2.0f, __fsub_rn(am1, ap1c));
        a2 = __fsub_rn(__fsub_rn(ap1, am1c), s2a);
    } else {                          // peak
        float A  = __nv_powf(10.0f, __fdiv_rn(gdb, 40.0f));
        float fc = denorm_log_f(fn, F_LOG_PK_LO, F_LOG_PK_D);
        float w0 = __fdiv_rn(__fmul_rn(F_2PI, fc), F_FS);
        float al = __fdiv_rn(__nv_sinf(w0), __fmul_rn(2.0f, Q));
        float c  = __nv_cosf(w0);
        float aA  = __fmul_rn(al, A);
        float adA = __fdiv_rn(al, A);
        b0 = __fadd_rn(1.0f, aA);
        b1 = __fmul_rn(-2.0f, c);
        b2 = __fsub_rn(1.0f, aA);
        a0 = __fadd_rn(1.0f, adA);
        a1 = __fmul_rn(-2.0f, c);
        a2 = __fsub_rn(1.0f, adA);
    }

    float nb0 = __fdiv_rn(b0, a0);
    float nb1 = __fdiv_rn(b1, a0);
    float nb2 = __fdiv_rn(b2, a0);
    float na1 = __fdiv_rn(a1, a0);
    float na2 = __fdiv_rn(a2, a0);

    // state-form feed constants (fp64 intermediate, rounded to f32):
    // k1 = b1 - a1*b0, k2 = b2 - a2*b0  (zeros-only perturbation)
    float k1 = (float)((double)nb1 - (double)na1*(double)nb0);
    float k2 = (float)((double)nb2 - (double)na2*(double)nb0);

    g_cAf[tid] = make_float4(nb0, k1, k2, na1);
    g_cBf[tid] = na2;

    // T = [[-a1,1],[-a2,0]]; powers T^(64*2^d), d=0..7, fp64.
    double ia1=(double)na1, ia2=(double)na2;
    double m00=-ia1, m01=1.0, m10=-ia2, m11=0.0;
    for (int k=0;k<6;k++){
        double n00 = m00*m00 + m01*m10, n01 = m00*m01 + m01*m11;
        double n10 = m10*m00 + m11*m10, n11 = m10*m01 + m11*m11;
        m00=n00;m01=n01;m10=n10;m11=n11;
    }
    double t00=0,t01=0,t10=0,t11=0;   // Tb = T^8192 (captured at d=7)
    for (int d=0;d<8;d++){
        double4 w; w.x=m00; w.y=m01; w.z=m10; w.w=m11;
        g_Wd[tid*8+d] = w;
        if (d == 7) { t00=m00; t01=m01; t10=m10; t11=m11; }
        double n00 = m00*m00 + m01*m10, n01 = m00*m01 + m01*m11;
        double n10 = m10*m00 + m11*m10, n11 = m10*m01 + m11*m11;
        m00=n00;m01=n01;m10=n10;m11=n11;
    }
    // Tb^j, j=0..31
    double p00=1.0, p01=0.0, p10=0.0, p11=1.0;
    for (int j=0;j<32;j++){
        double4 w; w.x=p00; w.y=p01; w.z=p10; w.w=p11;
        g_Tpow[tid*32+j] = w;
        double n00 = t00*p00 + t01*p10, n01 = t00*p01 + t01*p11;
        double n10 = t10*p00 + t11*p10, n11 = t10*p01 + t11*p11;
        p00=n00;p01=n01;p10=n10;p11=n11;
    }
    for (int c=0;c<NCHUNK;c++) g_flag[tid*NCHUNK + c] = 0;
    if (stage == 0) {
        float indb  = __fadd_rn(-60.0f, __fmul_rn(p[48], 60.0f));
        float outdb = __fadd_rn(-60.0f, __fmul_rn(p[49], 60.0f));
        g_ginf[row]  = __nv_powf(10.0f, __fdiv_rn(indb, 20.0f));
        g_goutf[row] = __nv_powf(10.0f, __fdiv_rn(outdb, 20.0f));
    }
}

// ---------------------------------------------------------------------------
// Fused kernel: state-form fp32 recursion (1-FFMA/4-cyc serial chain instead
// of 2-FFMA/8-cyc), shuffle scan, early publish, parallel lookback.
// ---------------------------------------------------------------------------
__global__ void __launch_bounds__(TPB)
fused_kernel(const float* __restrict__ audio, float* __restrict__ out)
{
    __shared__ float   sx[LSUB*PAD];        // resident sample tile (~33 KB)
    __shared__ double4 sW[2][8];            // double-buffered stage matrices
    __shared__ double  sWT1[4], sWT2[4];    // warp totals
    __shared__ double  sS1[4], sS2[4];      // per-warp block prefixes
    __shared__ double  sEntry[2];           // block entry state from lookback

    int bx    = blockIdx.x;
    int row   = bx & (NB-1);
    int chunk = bx >> 4;
    int t     = threadIdx.x;
    int wid   = t >> 5;
    int lane  = t & 31;

    size_t base = (size_t)row*NSAMP + (size_t)chunk*CHUNK;
    float ginf  = g_ginf[row];
    float goutf = g_goutf[row];

    // one-time coalesced load + transpose, with f32 input gain (as reference)
    for (int k = t; k < CHUNK; k += TPB) {
        float x = __fmul_rn(audio[base + k], ginf);
        sx[(k & (LSUB-1))*PAD + (k >> 6)] = x;
    }
    if (t < 8) sW[0][t] = g_Wd[(0*NB + row)*8 + t];
    __syncthreads();

    for (int stage = 0; stage < NSTAGE; stage++) {
        int rs = stage*NB + row;
        int buf = stage & 1;

        float4 c4 = g_cAf[rs];
        float b0=c4.x, k1=c4.y, k2=c4.z, na1=-c4.w;   // na1 = -a1
        float na2 = -g_cBf[rs];                        // na2 = -a2

        if (stage+1 < NSTAGE && t < 8)
            sW[buf^1][t] = g_Wd[((stage+1)*NB + row)*8 + t];

        // ---- pass 1: state-form fp32 recursion from zero state ------------
        // s1' = na1*s1 + (k1*x + s2); s2' = na2*s1 + k2*x  (chain: 1 FFMA)
        float s1 = 0.f, s2 = 0.f;
        #pragma unroll 8
        for (int i = 0; i < LSUB; i++) {
            float x  = sx[i*PAD + t];
            float t1 = fmaf(k1, x, s2);
            s2 = fmaf(na2, s1, k2*x);
            s1 = fmaf(na1, s1, t1);
        }
        double v1 = (double)s1, v2 = (double)s2;

        // ---- intra-warp affine scan, fp64, via shuffles --------------------
        #pragma unroll
        for (int d = 0; d < 5; d++) {
            int o = 1 << d;
            double p1 = __shfl_up_sync(0xffffffffu, v1, o);
            double p2 = __shfl_up_sync(0xffffffffu, v2, o);
            if (lane >= o) {
                double4 W = sW[buf][d];
                v1 = fma(W.x, p1, fma(W.y, p2, v1));
                v2 = fma(W.z, p1, fma(W.w, p2, v2));
            }
        }
        double pl1 = __shfl_up_sync(0xffffffffu, v1, 1);
        double pl2 = __shfl_up_sync(0xffffffffu, v2, 1);
        if (lane == 0) { pl1 = 0.0; pl2 = 0.0; }

        if (lane == 31) { sWT1[wid] = v1; sWT2[wid] = v2; }
        __syncthreads();                           // bar 1: warp totals ready

        // ---- warp 1: combine warp totals, publish aggregate EARLY ---------
        if (wid == 1) {
            if (lane == 0) {
                double4 W5 = sW[buf][5];           // T^2048
                double a1s = 0.0, a2s = 0.0;
                #pragma unroll
                for (int w = 0; w < 4; w++) {
                    sS1[w] = a1s; sS2[w] = a2s;
                    double n1 = fma(W5.x, a1s, fma(W5.y, a2s, sWT1[w]));
                    double n2 = fma(W5.z, a1s, fma(W5.w, a2s, sWT2[w]));
                    a1s = n1; a2s = n2;
                }
                int aidx = rs*NCHUNK + chunk;
                g_agg[2*aidx+0] = a1s;
                g_agg[2*aidx+1] = a2s;
                __threadfence();
                atomicExch(&g_flag[aidx], 1);
            }
            __syncwarp();
        }

        // ---- warp 0: PARALLEL lookback (lane t: Tb^(c-1-t) * V_t) ---------
        if (wid == 0) {
            double e1 = 0.0, e2 = 0.0;
            if (chunk > 0) {
                if (lane < chunk) {
                    int idx = rs*NCHUNK + lane;
                    volatile int* fl = g_flag;
                    while (fl[idx] == 0) __nanosleep(40);
                    __threadfence();
                    volatile double* ag = g_agg;
                    double u1 = ag[2*idx+0];
                    double u2 = ag[2*idx+1];
                    double4 M = g_Tpow[rs*32 + (chunk-1-lane)];
                    e1 = fma(M.x, u1, M.y*u2);
                    e2 = fma(M.z, u1, M.w*u2);
                }
                #pragma unroll
                for (int off = 16; off > 0; off >>= 1) {
                    e1 += __shfl_down_sync(0xffffffffu, e1, off);
                    e2 += __shfl_down_sync(0xffffffffu, e2, off);
                }
            }
            if (lane == 0) { sEntry[0] = e1; sEntry[1] = e2; }
        }
        __syncthreads();                           // bar 2: sEntry + sS ready

        // ---- per-thread entry: u_{l-1} + T^(64l)*(S_w + T^(2048w)*e) ------
        double e1 = sEntry[0], e2 = sEntry[1];
        if (wid & 1) {
            double4 W = sW[buf][5];
            double n1 = fma(W.x, e1, W.y*e2);
            double n2 = fma(W.z, e1, W.w*e2);
            e1 = n1; e2 = n2;
        }
        if (wid & 2) {
            double4 W = sW[buf][6];
            double n1 = fma(W.x, e1, W.y*e2);
            double n2 = fma(W.z, e1, W.w*e2);
            e1 = n1; e2 = n2;
        }
        e1 += sS1[wid];
        e2 += sS2[wid];
        #pragma unroll
        for (int d = 0; d < 5; d++) {
            if (lane & (1 << d)) {
                double4 W = sW[buf][d];
                double n1 = fma(W.x, e1, W.y*e2);
                double n2 = fma(W.z, e1, W.w*e2);
                e1 = n1; e2 = n2;
            }
        }
        s1 = (float)(e1 + pl1);
        s2 = (float)(e2 + pl2);

        // ---- replay state-form fp32 recursion, write y ---------------------
        #pragma unroll 8
        for (int i = 0; i < LSUB; i++) {
            float x  = sx[i*PAD + t];
            float y  = fmaf(b0, x, s1);
            float t1 = fmaf(k1, x, s2);
            s2 = fmaf(na2, s1, k2*x);
            s1 = fmaf(na1, s1, t1);
            sx[i*PAD + t] = y;
        }
        __syncthreads();                           // bar 3: sx for next stage
    }

    // one-time coalesced store with f32 output gain (as reference)
    for (int k = t; k < CHUNK; k += TPB)
        out[base + k] = __fmul_rn(sx[(k & (LSUB-1))*PAD + (k >> 6)], goutf);
}

// ---------------------------------------------------------------------------
extern "C" void kernel_launch(void* const* d_in, const int* in_sizes, int n_in,
                              void* d_out, int out_size)
{
    const float* audio  = (const float*)d_in[0];   // [16, 262144] f32
    const float* params = (const float*)d_in[1];   // [16, 50]     f32
    float* out = (float*)d_out;

    coef_kernel<<<1, NSTAGE*NB>>>(params);
    fused_kernel<<<NB*NCHUNK, TPB>>>(audio, out);
}